// round 10
// baseline (speedup 1.0000x reference)
#include <cuda_runtime.h>
#include <math.h>

#define NL 24
#define NHD 16
#define HD 64
#define DM 1024
#define FF 4096
#define VOC 8194
#define TPAST 2047
#define TKV 2048
#define NB 148
#define NT 1024
#define KS_ELEMS (NL*NHD*HD*TKV)   /* 50331648 */

// ---------------- persistent scratch (device globals; no allocations) ----------------
__device__ __align__(16) float g_hbuf[2][DM];     // residual ping-pong
__device__ __align__(16) float g_qkv[3*DM];       // q | k_new | v_new
__device__ __align__(16) float g_h2[DM];          // bo + h + attn_out
__device__ float g_m[NHD][8];
__device__ float g_se[NHD][8];
__device__ __align__(16) float g_acc[NHD][8][HD];
__device__ unsigned g_count = 0;
__device__ volatile unsigned g_sense = 0;
__device__ unsigned long long g_best = 0ull;
// flags (reset at kernel end)
__device__ unsigned g_dInit;
__device__ unsigned g_dA[NL], g_dB[NL], g_dC[NL], g_dD[NL];
__device__ unsigned g_fQB[NL], g_fH2[NL], g_fHN[NL];
__device__ unsigned g_dAqh[NL][NHD];   // q per head, target 2
__device__ unsigned g_dAkvh[NL][NHD];  // k_new/v_new per head, target 4
__device__ unsigned g_dBh[NL][NHD];    // attention chunks per head, target 8

__device__ __forceinline__ void gbar() {
    __syncthreads();
    if (threadIdx.x == 0) {
        __threadfence();
        unsigned cur = g_sense;
        if (atomicAdd(&g_count, 1u) == NB - 1u) {
            g_count = 0u;
            __threadfence();
            g_sense = cur + 1u;
        } else {
            while (g_sense == cur) __nanosleep(32);
        }
        __threadfence();
    }
    __syncthreads();
}

__device__ __forceinline__ void waitf(unsigned* f, unsigned tgt) {
    if (threadIdx.x == 0) {
        volatile unsigned* vf = (volatile unsigned*)f;
        while (*vf < tgt) __nanosleep(40);
    }
    __syncthreads();
}

__device__ __forceinline__ void pf_l2(const void* p) {
    asm volatile("prefetch.global.L2 [%0];" :: "l"(p));
}

__device__ __forceinline__ void f4add(float4& a, float4 b) {
    a.x += b.x; a.y += b.y; a.z += b.z; a.w += b.w;
}
__device__ __forceinline__ void f4fma(float4& a, float s, float4 w) {
    a.x += s * w.x; a.y += s * w.y; a.z += s * w.z; a.w += s * w.w;
}
__device__ __forceinline__ float4 f4shfl_add(float4 a, int o) {
    a.x += __shfl_xor_sync(0xffffffffu, a.x, o);
    a.y += __shfl_xor_sync(0xffffffffu, a.y, o);
    a.z += __shfl_xor_sync(0xffffffffu, a.z, o);
    a.w += __shfl_xor_sync(0xffffffffu, a.w, o);
    return a;
}
__device__ __forceinline__ float4 f4warp_sum(float4 a) {
    #pragma unroll
    for (int o = 16; o; o >>= 1) a = f4shfl_add(a, o);
    return a;
}
__device__ __forceinline__ float gelu_tanh(float x) {
    float x3 = x * x * x;
    float t = tanhf(0.7978845608028654f * (x + 0.044715f * x3));
    return 0.5f * x * (1.0f + t);
}

__device__ __forceinline__ void ln_stats(float v, float* SR, int tid,
                                         float& mean, float& rstd) {
    float a = v, b = v * v;
    #pragma unroll
    for (int o = 16; o; o >>= 1) {
        a += __shfl_xor_sync(0xffffffffu, a, o);
        b += __shfl_xor_sync(0xffffffffu, b, o);
    }
    int w = tid >> 5, lane = tid & 31;
    if (lane == 0) { SR[w] = a; SR[32 + w] = b; }
    __syncthreads();
    if (w == 0) {
        a = SR[lane]; b = SR[32 + lane];
        #pragma unroll
        for (int o = 16; o; o >>= 1) {
            a += __shfl_xor_sync(0xffffffffu, a, o);
            b += __shfl_xor_sync(0xffffffffu, b, o);
        }
        if (lane == 0) { SR[0] = a; SR[32] = b; }
    }
    __syncthreads();
    mean = SR[0] * (1.0f / DM);
    float var = SR[32] * (1.0f / DM) - mean * mean;
    rstd = rsqrtf(var + 1e-5f);
}

__device__ __forceinline__ void ln_vec(const float* __restrict__ vec,
                                       const float* __restrict__ gw,
                                       const float* __restrict__ bw,
                                       float* SX, float* SR, int tid) {
    float v = __ldcg(&vec[tid]);
    float mean, rstd;
    ln_stats(v, SR, tid, mean, rstd);
    SX[tid] = (v - mean) * rstd * __ldg(&gw[tid]) + __ldg(&bw[tid]);
    __syncthreads();
}

__global__ void __launch_bounds__(NT, 1) tts_decode_kernel(
    const float* __restrict__ past_k, const float* __restrict__ past_v,
    const float* __restrict__ hidden, const float* __restrict__ logits_scale,
    const float* __restrict__ mask_scale,
    const float* __restrict__ ln1_g, const float* __restrict__ ln1_b,
    const float* __restrict__ Wq, const float* __restrict__ bq,
    const float* __restrict__ Wk, const float* __restrict__ bk,
    const float* __restrict__ Wv, const float* __restrict__ bv,
    const float* __restrict__ Wo, const float* __restrict__ bo,
    const float* __restrict__ ln2_g, const float* __restrict__ ln2_b,
    const float* __restrict__ Wfc, const float* __restrict__ bfc,
    const float* __restrict__ Wmp, const float* __restrict__ bmp,
    const float* __restrict__ lnf_g, const float* __restrict__ lnf_b,
    const float* __restrict__ lm_w,
    float* __restrict__ out)
{
    __shared__ __align__(16) float sm[1024*4 + 4160 + 512 + 64];
    extern __shared__ __align__(16) float smdyn[];   // 128KB: K+V tiles / Wfc tile
    float* SX  = sm;                 // 1024: raw vec / q
    float* SP  = sm + 1024;          // 1024: v*g
    float* SG  = sm + 2048;          // 1024: g
    float* SB  = sm + 3072;          // 1024: b
    float* S4F = sm + 4096;          // 4160: reduce scratch
    float4* S4 = (float4*)S4F;
    float* SC  = sm + 8256;          // 512: probs / gelu / combine
    float* SR  = sm + 8768;          // 64: shuffle partials
    float*  KS  = smdyn;                       // [64][256] floats (64KB)
    float4* VS  = (float4*)(smdyn + 16384);    // [256][16] float4 (64KB)
    float4* WfS = (float4*)smdyn;              // [8192] float4 (128KB), phase 2

    const int tid = threadIdx.x;
    const int bid = blockIdx.x;
    const int lane = tid & 31;
    const int w = tid >> 5;
    const float mskc = -128.0f * __ldg(&mask_scale[0]);
    const unsigned sdyn = (unsigned)__cvta_generic_to_shared(smdyn);

    // ---------------- init (flag-signaled) ----------------
    if (bid == 0) {
        g_hbuf[0][tid] = __ldg(&hidden[tid]);
        __threadfence(); __syncthreads();
        if (tid == 0) atomicAdd(&g_dInit, 1u);
    } else if (bid >= 1 && bid <= 3) {
        int mat = bid - 1;
        const float* bb = (mat == 0) ? bq : ((mat == 1) ? bk : bv);
        g_qkv[mat * DM + tid] = __ldg(&bb[tid]);
        __threadfence(); __syncthreads();
        if (tid == 0) atomicAdd(&g_fQB[0], 1u);
    } else if (bid == 129) {
        g_hbuf[1][tid] = __ldg(&bmp[0 * DM + tid]);   // seed layer-0 h_next
        __threadfence(); __syncthreads();
        if (tid == 0) atomicAdd(&g_fHN[0], 1u);
    }

    for (int l = 0; l < NL; l++) {
        const int p = l & 1;
        const float* h_in = g_hbuf[p];
        float* h_next = g_hbuf[p ^ 1];

        // ====== layer prologue: cp.async-stage K+V tiles (blocks <128), no waits ======
        if (bid < 128) {
            int h = bid >> 3, c = bid & 7;
            int t0 = c * 256;
            {
                int t = tid & 255, eg = tid >> 8;
                int tg = t0 + t;
                if (tg < TPAST) {
                    size_t kb = ((size_t)(l * NHD + h) * HD) * TPAST;
                    #pragma unroll
                    for (int j = 0; j < 16; j++) {
                        int e = eg * 16 + j;
                        asm volatile("cp.async.ca.shared.global [%0], [%1], 4;"
                                     :: "r"(sdyn + (unsigned)((e * 256 + t) * 4)),
                                        "l"(&past_k[kb + (size_t)e * TPAST + tg]));
                    }
                }
            }
            {
                int e4 = tid & 15, tgr = tid >> 4;
                const float4* pv4 = (const float4*)(past_v + ((size_t)(l * NHD + h) * TPAST) * HD);
                #pragma unroll
                for (int i = 0; i < 4; i++) {
                    int ti = tgr + 64 * i;
                    int tgl = t0 + ti;
                    if (tgl < TPAST)
                        asm volatile("cp.async.cg.shared.global [%0], [%1], 16;"
                                     :: "r"(sdyn + 65536u + (unsigned)((ti * 16 + e4) * 16)),
                                        "l"(&pv4[(size_t)tgl * 16 + e4]));
                }
            }
            asm volatile("cp.async.commit_group;");
        }

        // ====== block 128: g_h2 = bo + h_in ======
        if (bid == 128) {
            waitf((l == 0) ? &g_dInit : &g_dD[l - 1], (l == 0) ? 1u : 129u);
            g_h2[tid] = __ldg(&bo[l * DM + tid]) + __ldcg(&h_in[tid]);
            __threadfence(); __syncthreads();
            if (tid == 0) atomicAdd(&g_fH2[l], 1u);
        }
        // ====== block 129: seed h_next = bmp (l>=1) ======
        if (bid == 129 && l >= 1) {
            waitf(&g_dA[l - 1], 96u);
            waitf(&g_fH2[l - 1], 1u);
            h_next[tid] = __ldg(&bmp[l * DM + tid]);
            __threadfence(); __syncthreads();
            if (tid == 0) atomicAdd(&g_fHN[l], 1u);
        }

        // ====== Stage A: QKV (96 blocks), LN linearized ======
        if (bid < 96) {
            int mat = bid % 3, rest = bid / 3, h = rest % NHD, half = rest / NHD;
            const float4* W4 = (const float4*)(
                ((mat == 0) ? Wq : ((mat == 1) ? Wk : Wv))
                + (size_t)l * NHD * DM * HD + (size_t)h * DM * HD);
            int d0 = half * 512;
            int e4 = tid & 15, dg = tid >> 4;
            float4 wa[4];
            #pragma unroll
            for (int it = 0; it < 4; it++)
                wa[it] = __ldcs(&W4[(size_t)(d0 + dg + it * 64) * 16 + e4]);
            #pragma unroll
            for (int it = 4; it < 8; it++)
                pf_l2(&W4[(size_t)(d0 + dg + it * 64) * 16 + e4]);
            float gg = __ldg(&ln1_g[l * DM + tid]);
            float bb = __ldg(&ln1_b[l * DM + tid]);
            waitf((l == 0) ? &g_dInit : &g_dD[l - 1], (l == 0) ? 1u : 129u);
            float v = __ldcg(&h_in[tid]);
            SP[tid] = v * gg; SG[tid] = gg; SB[tid] = bb;
            __syncthreads();
            float mean, rstd;
            ln_stats(v, SR, tid, mean, rstd);
            float4 aA = make_float4(0,0,0,0), aB = aA, aC = aA;
            #pragma unroll
            for (int it = 0; it < 4; it++) {
                int d = d0 + dg + it * 64;
                f4fma(aA, SP[d], wa[it]); f4fma(aB, SG[d], wa[it]); f4fma(aC, SB[d], wa[it]);
            }
            #pragma unroll
            for (int it = 4; it < 8; it++) {
                int d = d0 + dg + it * 64;
                float4 ww = __ldcs(&W4[(size_t)d * 16 + e4]);
                f4fma(aA, SP[d], ww); f4fma(aB, SG[d], ww); f4fma(aC, SB[d], ww);
            }
            float4 aD;       // fold LN before the tree
            aD.x = rstd * (aA.x - mean * aB.x) + aC.x;
            aD.y = rstd * (aA.y - mean * aB.y) + aC.y;
            aD.z = rstd * (aA.z - mean * aB.z) + aC.z;
            aD.w = rstd * (aA.w - mean * aB.w) + aC.w;
            aD = f4shfl_add(aD, 16);
            if (lane < 16) S4[w * 17 + lane] = aD;
            waitf(&g_fQB[l], 3u);                     // syncs; S4 visible
            if (w < 16) {
                float4 t = f4warp_sum(S4[lane * 17 + w]);
                if (lane == 0) {
                    float* dst = &g_qkv[mat * DM + h * HD + w * 4];
                    atomicAdd(dst,     t.x); atomicAdd(dst + 1, t.y);
                    atomicAdd(dst + 2, t.z); atomicAdd(dst + 3, t.w);
                }
            }
            __threadfence(); __syncthreads();
            if (tid == 0) {
                atomicAdd(&g_dA[l], 1u);
                if (mat == 0) atomicAdd(&g_dAqh[l][h], 1u);
                else          atomicAdd(&g_dAkvh[l][h], 1u);
            }
        }

        // ====== Stage B: attention (128 blocks), K/V from smem ======
        if (bid < 128) {
            int h = bid >> 3, c = bid & 7;
            int t0 = c * 256;
            int t = tid & 255, eg = tid >> 8;
            int tg = t0 + t;
            size_t okbase = ((size_t)(l * NHD + h) * HD) * TKV;
            const bool isNew = (tg >= TPAST);
            waitf(&g_dAqh[l][h], 2u);                 // q ready (2 producers)
            if (c == 7) waitf(&g_dAkvh[l][h], 4u);    // k_new/v_new ready
            asm volatile("cp.async.wait_group 0;" ::: "memory");  // K/V tiles landed
            if (tid < 64) SX[tid] = __ldcg(&g_qkv[h * HD + tid]); // q
            __syncthreads();
            float part = 0.0f;
            if (!isNew) {
                #pragma unroll
                for (int j = 0; j < 16; j++) {
                    int e = eg * 16 + j;
                    float kv = KS[e * 256 + t];
                    __stcs(&out[okbase + (size_t)e * TKV + tg], kv);
                    part += SX[e] * kv;
                }
            } else {
                #pragma unroll
                for (int j = 0; j < 16; j++) {
                    int e = eg * 16 + j;
                    float kv = __ldcg(&g_qkv[DM + h * HD + e]);
                    __stcs(&out[okbase + (size_t)e * TKV + tg], kv);
                    part += SX[e] * kv;
                }
            }
            S4F[eg * 256 + t] = part;
            __syncthreads();

            float sc = -1e30f;
            if (tid < 256) {
                sc = S4F[t] + S4F[256 + t] + S4F[512 + t] + S4F[768 + t];
                if (tg > 0) sc += mskc;
            }
            float mx = sc;
            #pragma unroll
            for (int o = 16; o; o >>= 1) mx = fmaxf(mx, __shfl_xor_sync(0xffffffffu, mx, o));
            if (lane == 0) SR[w] = mx;
            __syncthreads();
            if (w == 0) {
                float m2 = (lane < 8) ? SR[lane] : -1e30f;
                #pragma unroll
                for (int o = 16; o; o >>= 1) m2 = fmaxf(m2, __shfl_xor_sync(0xffffffffu, m2, o));
                if (lane == 0) SR[40] = m2;
            }
            __syncthreads();
            float M = SR[40];
            float pe = 0.0f;
            if (tid < 256) { pe = __expf(sc - M); SC[t] = pe; }
            float sum = pe;
            #pragma unroll
            for (int o = 16; o; o >>= 1) sum += __shfl_xor_sync(0xffffffffu, sum, o);
            if (lane == 0) SR[w] = sum;
            __syncthreads();
            if (w == 0) {
                float s2 = (lane < 8) ? SR[lane] : 0.0f;
                #pragma unroll
                for (int o = 16; o; o >>= 1) s2 += __shfl_xor_sync(0xffffffffu, s2, o);
                if (lane == 0) SR[41] = s2;
            }
            __syncthreads();

            // P.V from smem V + fused copy
            int e4 = tid & 15, tgr = tid >> 4;
            float4* ov4 = (float4*)(out + (size_t)KS_ELEMS + ((size_t)(l * NHD + h) * TKV) * HD);
            const float4* vnew4 = (const float4*)(g_qkv + 2 * DM + h * HD);
            float4 acc = make_float4(0,0,0,0);
            #pragma unroll
            for (int i = 0; i < 4; i++) {
                int ti = tgr + 64 * i;
                int tgl = t0 + ti;
                float4 vv = (tgl < TPAST) ? VS[ti * 16 + e4] : __ldcg(&vnew4[e4]);
                __stcs(&ov4[(size_t)tgl * 16 + e4], vv);
                f4fma(acc, SC[ti], vv);
            }
            acc = f4shfl_add(acc, 16);
            if (lane < 16) S4[w * 17 + lane] = acc;
            __syncthreads();
            if (tid == 0) { __stcg(&g_m[h][c], M); __stcg(&g_se[h][c], SR[41]); }
            if (w < 16) {
                float4 t2 = f4warp_sum(S4[lane * 17 + w]);
                if (lane == 0) __stcg((float4*)&g_acc[h][c][w * 4], t2);
            }
            __threadfence(); __syncthreads();
            if (tid == 0) { atomicAdd(&g_dBh[l][h], 1u); atomicAdd(&g_dB[l], 1u); }
        }

        // ====== blocks 130-132: seed next layer's qkv bias ======
        if (bid >= 130 && bid <= 132 && (l + 1) < NL) {
            waitf(&g_dB[l], 128u);
            int mat = bid - 130;
            const float* bb = (mat == 0) ? bq : ((mat == 1) ? bk : bv);
            g_qkv[mat * DM + tid] = __ldg(&bb[(l + 1) * DM + tid]);
            __threadfence(); __syncthreads();
            if (tid == 0) atomicAdd(&g_fQB[l + 1], 1u);
        }

        // ====== Stage C: combine + c_proj (128 blocks x 8 rows) ======
        if (bid < 128) {
            int r0 = bid * 8, h = r0 >> 6, e0 = r0 & 63;
            // cp.async-stage the full Wfc tile (K/V fully consumed; synced since)
            {
                int qx = tid & 7, dgx = tid >> 3;
                const float4* Wf4p = (const float4*)(Wfc + (size_t)l * DM * FF);
                #pragma unroll
                for (int it = 0; it < 8; it++) {
                    int d = dgx + it * 128;
                    asm volatile("cp.async.cg.shared.global [%0], [%1], 16;"
                                 :: "r"(sdyn + (unsigned)((d * 8 + qx) * 16)),
                                    "l"(&Wf4p[(size_t)d * 1024 + bid * 8 + qx]));
                }
                asm volatile("cp.async.commit_group;");
            }
            {   // L2 prefetch Wmp tile (proven winner)
                int c4x = tid & 255, jgx = tid >> 8;
                const float4* Wm4p = (const float4*)(Wmp + (size_t)l * FF * DM + (size_t)(bid * 32) * DM);
                #pragma unroll
                for (int jj = 0; jj < 8; jj++)
                    pf_l2(&Wm4p[(size_t)(jgx + 4 * jj) * 256 + c4x]);
            }
            int c4 = tid & 255, jg = tid >> 8;
            const float4* Wo4 = (const float4*)(Wo + (size_t)l * DM * DM + (size_t)r0 * DM);
            float4 wo0 = __ldcs(&Wo4[(size_t)jg * 256 + c4]);
            float4 wo1 = __ldcs(&Wo4[(size_t)(jg + 4) * 256 + c4]);
            waitf(&g_dBh[l][h], 8u);                  // this head's chunks only
            if (tid < 32) {
                float m = (lane < 8) ? __ldcg(&g_m[h][lane]) : -1e30f;
                float M = m;
                #pragma unroll
                for (int o = 16; o; o >>= 1) M = fmaxf(M, __shfl_xor_sync(0xffffffffu, M, o));
                float wc  = (lane < 8) ? __expf(m - M) : 0.0f;
                float den = (lane < 8) ? wc * __ldcg(&g_se[h][lane]) : 0.0f;
                #pragma unroll
                for (int o = 16; o; o >>= 1) den += __shfl_xor_sync(0xffffffffu, den, o);
                if (lane < 8) SC[lane] = wc;
                if (lane == 0) SC[8] = den;
            }
            __syncthreads();
            if (tid < 64) {
                int cc = tid >> 3, e8 = tid & 7;
                SC[16 + cc * 8 + e8] = SC[cc] * __ldcg(&g_acc[h][cc][e0 + e8]);
            }
            __syncthreads();
            if (tid < 8) {
                float s = 0.0f;
                #pragma unroll
                for (int cc = 0; cc < 8; cc++) s += SC[16 + cc * 8 + tid];
                SC[80 + tid] = s / SC[8];
            }
            __syncthreads();
            float4 acc = make_float4(0,0,0,0);
            f4fma(acc, SC[80 + jg], wo0);
            f4fma(acc, SC[80 + jg + 4], wo1);
            S4[jg * 256 + c4] = acc;
            #pragma unroll
            for (int s = 2; s; s >>= 1) {
                __syncthreads();
                if (jg < s) f4add(S4[jg * 256 + c4], S4[(jg + s) * 256 + c4]);
            }
            __syncthreads();
            waitf(&g_fH2[l], 1u);
            atomicAdd(&g_h2[tid], S4F[tid]);
            __threadfence(); __syncthreads();
            if (tid == 0) atomicAdd(&g_dC[l], 1u);
        }

        // ====== Stage DE: fused MLP (128 blocks), FC weights from smem ======
        if (bid < 128) {
            int q = tid & 7, dg = tid >> 3;
            float gg = __ldg(&ln2_g[l * DM + tid]);
            float bb = __ldg(&ln2_b[l * DM + tid]);
            waitf(&g_dC[l], 128u);
            float v = __ldcg(&g_h2[tid]);
            SP[tid] = v * gg; SG[tid] = gg; SB[tid] = bb;
            __syncthreads();
            float mean, rstd;
            ln_stats(v, SR, tid, mean, rstd);
            asm volatile("cp.async.wait_group 0;" ::: "memory");  // Wfc tile landed
            float4 aA = make_float4(0,0,0,0), aB = aA, aC = aA;
            #pragma unroll
            for (int it = 0; it < 8; it++) {
                int d = dg + it * 128;
                float4 ww = WfS[d * 8 + q];
                f4fma(aA, SP[d], ww); f4fma(aB, SG[d], ww); f4fma(aC, SB[d], ww);
            }
            float4 aD;
            aD.x = rstd * (aA.x - mean * aB.x) + aC.x;
            aD.y = rstd * (aA.y - mean * aB.y) + aC.y;
            aD.z = rstd * (aA.z - mean * aB.z) + aC.z;
            aD.w = rstd * (aA.w - mean * aB.w) + aC.w;
            aD = f4shfl_add(aD, 8);
            aD = f4shfl_add(aD, 16);
            if (lane < 8) S4[w * 9 + lane] = aD;
            // Wmp loads (L2-warm from stage-C prefetch) overlap FC tree
            int c4 = tid & 255, jg = tid >> 8;
            const float4* Wm4 = (const float4*)(Wmp + (size_t)l * FF * DM + (size_t)(bid * 32) * DM);
            float4 wm[8];
            #pragma unroll
            for (int jj = 0; jj < 8; jj++)
                wm[jj] = __ldcs(&Wm4[(size_t)(jg + 4 * jj) * 256 + c4]);
            __syncthreads();
            if (w < 8) {
                float4 t = f4warp_sum(S4[lane * 9 + w]);
                if (lane == 0) {
                    const float* bfp = &bfc[l * FF + bid * 32 + w * 4];
                    SC[w * 4 + 0] = gelu_tanh(t.x + __ldg(&bfp[0]));
                    SC[w * 4 + 1] = gelu_tanh(t.y + __ldg(&bfp[1]));
                    SC[w * 4 + 2] = gelu_tanh(t.z + __ldg(&bfp[2]));
                    SC[w * 4 + 3] = gelu_tanh(t.w + __ldg(&bfp[3]));
                }
            }
            __syncthreads();
            float4 acc2 = make_float4(0,0,0,0);
            #pragma unroll
            for (int jj = 0; jj < 8; jj++)
                f4fma(acc2, SC[jg + 4 * jj], wm[jj]);
            S4[jg * 256 + c4] = acc2;
            #pragma unroll
            for (int s = 2; s; s >>= 1) {
                __syncthreads();
                if (jg < s) f4add(S4[jg * 256 + c4], S4[(jg + s) * 256 + c4]);
            }
            __syncthreads();
            waitf(&g_fHN[l], 1u);
            atomicAdd(&h_next[tid], S4F[tid]);
            __threadfence(); __syncthreads();
            if (tid == 0) atomicAdd(&g_dD[l], 1u);
        }
        // block 128: residual h2 -> h_next
        if (bid == 128) {
            waitf(&g_dC[l], 128u);
            waitf(&g_fHN[l], 1u);
            atomicAdd(&h_next[tid], __ldcg(&g_h2[tid]));
            __threadfence(); __syncthreads();
            if (tid == 0) atomicAdd(&g_dD[l], 1u);    // total target 129
        }
    }

    // ====== Final: LN + logits (float2, shallow tree) + argmax ======
    waitf(&g_dD[NL - 1], 129u);
    ln_vec(g_hbuf[0], lnf_g, lnf_b, SX, SR, tid);
    if (bid == 0) {
        if (tid == 0) out[2 * (size_t)KS_ELEMS] = (float)TKV;
        out[2 * (size_t)KS_ELEMS + 1 + tid] = SX[tid];
    }
    {
        int cb = bid * 64;
        if (cb < VOC) {
            int c2 = lane, dg = w;
            int col = cb + c2 * 2;
            float2 acc = make_float2(0.f, 0.f);
            if (col < VOC) {
                const float2* L2p = (const float2*)lm_w;
                for (int d = dg; d < DM; d += 32) {
                    float xv = SX[d];
                    float2 wv = __ldcs(&L2p[(size_t)d * (VOC / 2) + (cb >> 1) + c2]);
                    acc.x += xv * wv.x; acc.y += xv * wv.y;
                }
            }
            S4F[dg * 65 + c2 * 2]     = acc.x;
            S4F[dg * 65 + c2 * 2 + 1] = acc.y;
            __syncthreads();
            float s0 = S4F[lane * 65 + 2 * w];
            float s1 = S4F[lane * 65 + 2 * w + 1];
            #pragma unroll
            for (int o = 16; o; o >>= 1) {
                s0 += __shfl_xor_sync(0xffffffffu, s0, o);
                s1 += __shfl_xor_sync(0xffffffffu, s1, o);
            }
            if (lane == 0) {
                #pragma unroll
                for (int k = 0; k < 2; k++) {
                    int col2 = cb + 2 * w + k;
                    if (col2 < VOC) {
                        float logit = (k ? s1 : s0) * __ldg(&logits_scale[col2]);
                        unsigned u = __float_as_uint(logit);
                        u = (u & 0x80000000u) ? ~u : (u | 0x80000000u);
                        unsigned long long key =
                            ((unsigned long long)u << 32) |
                            (unsigned long long)(0xFFFFFFFFu - (unsigned)col2);
                        atomicMax(&g_best, key);
                    }
                }
            }
        }
    }
    gbar();

    if (bid == 0) {
        if (tid == 0) {
            unsigned long long b = atomicMax(&g_best, 0ull);
            unsigned col = 0xFFFFFFFFu - (unsigned)(b & 0xFFFFFFFFull);
            out[2 * (size_t)KS_ELEMS + 1 + DM] = (float)col;
            g_best = 0ull;
            g_dInit = 0u;
        }
        if (tid < NL) {
            g_dA[tid] = 0u; g_dB[tid] = 0u; g_dC[tid] = 0u; g_dD[tid] = 0u;
            g_fQB[tid] = 0u; g_fH2[tid] = 0u; g_fHN[tid] = 0u;
        }
        if (tid < NL * NHD) {
            ((unsigned*)g_dAqh)[tid] = 0u;
            ((unsigned*)g_dAkvh)[tid] = 0u;
            ((unsigned*)g_dBh)[tid] = 0u;
        }
    }
}

extern "C" void kernel_launch(void* const* d_in, const int* in_sizes, int n_in,
                              void* d_out, int out_size) {
    const float* past_k       = (const float*)d_in[0];
    const float* past_v       = (const float*)d_in[1];
    const float* hidden       = (const float*)d_in[2];
    const float* logits_scale = (const float*)d_in[3];
    const float* mask_scale   = (const float*)d_in[4];
    const float* ln1_g        = (const float*)d_in[5];
    const float* ln1_b        = (const float*)d_in[6];
    const float* Wq           = (const float*)d_in[7];
    const float* bq           = (const float*)d_in[8];
    const float* Wk           = (const float*)d_in[9];
    const float* bk           = (const float*)d_in[10];
    const float* Wv           = (const float*)d_in[11];
    const float* bv           = (const float*)d_in[12];
    const float* Wo           = (const float*)d_in[13];
    const float* bo           = (const float*)d_in[14];
    const float* ln2_g        = (const float*)d_in[15];
    const float* ln2_b        = (const float*)d_in[16];
    const float* Wfc          = (const float*)d_in[17];
    const float* bfc          = (const float*)d_in[18];
    const float* Wmp          = (const float*)d_in[19];
    const float* bmp          = (const float*)d_in[20];
    const float* lnf_g        = (const float*)d_in[21];
    const float* lnf_b        = (const float*)d_in[22];
    const float* lm_w         = (const float*)d_in[23];
    float* outp = (float*)d_out;

    static const size_t DYN_SMEM = 128 * 1024;   // K+V / Wfc staging buffer
    cudaFuncSetAttribute(tts_decode_kernel,
                         cudaFuncAttributeMaxDynamicSharedMemorySize, (int)DYN_SMEM);
    tts_decode_kernel<<<NB, NT, DYN_SMEM>>>(past_k, past_v, hidden, logits_scale, mask_scale,
                                  ln1_g, ln1_b, Wq, bq, Wk, bk, Wv, bv, Wo, bo,
                                  ln2_g, ln2_b, Wfc, bfc, Wmp, bmp,
                                  lnf_g, lnf_b, lm_w, outp);
}

// round 12
// speedup vs baseline: 1.1873x; 1.1873x over previous
#include <cuda_runtime.h>
#include <math.h>

#define NL 24
#define NHD 16
#define HD 64
#define DM 1024
#define FF 4096
#define VOC 8194
#define TPAST 2047
#define TKV 2048
#define NB 148
#define NT 1024
#define KS_ELEMS (NL*NHD*HD*TKV)   /* 50331648 */

// ---------------- persistent scratch (device globals; no allocations) ----------------
__device__ __align__(16) float g_hbuf[2][DM];     // residual ping-pong
__device__ __align__(16) float g_qkv[3*DM];       // q | k_new | v_new
__device__ __align__(16) float g_h2[DM];          // bo + h + attn_out
__device__ float g_m[NHD][8];
__device__ float g_se[NHD][8];
__device__ __align__(16) float g_acc[NHD][8][HD];
__device__ unsigned g_count = 0;
__device__ volatile unsigned g_sense = 0;
__device__ unsigned long long g_best = 0ull;
// flags (reset at kernel end)
__device__ unsigned g_dInit;
__device__ unsigned g_dA[NL], g_dB[NL], g_dC[NL], g_dD[NL];
__device__ unsigned g_fQB[NL], g_fH2[NL], g_fHN[NL];
__device__ unsigned g_dAqh[NL][NHD];   // q per head, target 2
__device__ unsigned g_dAkvh[NL][NHD];  // k_new/v_new per head, target 4
__device__ unsigned g_dBh[NL][NHD];    // attention chunks per head, target 8

__device__ __forceinline__ void gbar() {
    __syncthreads();
    if (threadIdx.x == 0) {
        __threadfence();
        unsigned cur = g_sense;
        if (atomicAdd(&g_count, 1u) == NB - 1u) {
            g_count = 0u;
            __threadfence();
            g_sense = cur + 1u;
        } else {
            while (g_sense == cur) __nanosleep(32);
        }
        __threadfence();
    }
    __syncthreads();
}

__device__ __forceinline__ void waitf(unsigned* f, unsigned tgt) {
    if (threadIdx.x == 0) {
        volatile unsigned* vf = (volatile unsigned*)f;
        while (*vf < tgt) __nanosleep(40);
    }
    __syncthreads();
}

__device__ __forceinline__ void pf_l2(const void* p) {
    asm volatile("prefetch.global.L2 [%0];" :: "l"(p));
}

__device__ __forceinline__ void f4add(float4& a, float4 b) {
    a.x += b.x; a.y += b.y; a.z += b.z; a.w += b.w;
}
__device__ __forceinline__ void f4fma(float4& a, float s, float4 w) {
    a.x += s * w.x; a.y += s * w.y; a.z += s * w.z; a.w += s * w.w;
}
__device__ __forceinline__ float4 f4shfl_add(float4 a, int o) {
    a.x += __shfl_xor_sync(0xffffffffu, a.x, o);
    a.y += __shfl_xor_sync(0xffffffffu, a.y, o);
    a.z += __shfl_xor_sync(0xffffffffu, a.z, o);
    a.w += __shfl_xor_sync(0xffffffffu, a.w, o);
    return a;
}
__device__ __forceinline__ float4 f4warp_sum(float4 a) {
    #pragma unroll
    for (int o = 16; o; o >>= 1) a = f4shfl_add(a, o);
    return a;
}
__device__ __forceinline__ float gelu_tanh(float x) {
    float x3 = x * x * x;
    float t = tanhf(0.7978845608028654f * (x + 0.044715f * x3));
    return 0.5f * x * (1.0f + t);
}

__device__ __forceinline__ void ln_stats(float v, float* SR, int tid,
                                         float& mean, float& rstd) {
    float a = v, b = v * v;
    #pragma unroll
    for (int o = 16; o; o >>= 1) {
        a += __shfl_xor_sync(0xffffffffu, a, o);
        b += __shfl_xor_sync(0xffffffffu, b, o);
    }
    int w = tid >> 5, lane = tid & 31;
    if (lane == 0) { SR[w] = a; SR[32 + w] = b; }
    __syncthreads();
    if (w == 0) {
        a = SR[lane]; b = SR[32 + lane];
        #pragma unroll
        for (int o = 16; o; o >>= 1) {
            a += __shfl_xor_sync(0xffffffffu, a, o);
            b += __shfl_xor_sync(0xffffffffu, b, o);
        }
        if (lane == 0) { SR[0] = a; SR[32] = b; }
    }
    __syncthreads();
    mean = SR[0] * (1.0f / DM);
    float var = SR[32] * (1.0f / DM) - mean * mean;
    rstd = rsqrtf(var + 1e-5f);
}

__device__ __forceinline__ void ln_vec(const float* __restrict__ vec,
                                       const float* __restrict__ gw,
                                       const float* __restrict__ bw,
                                       float* SX, float* SR, int tid) {
    float v = __ldcg(&vec[tid]);
    float mean, rstd;
    ln_stats(v, SR, tid, mean, rstd);
    SX[tid] = (v - mean) * rstd * __ldg(&gw[tid]) + __ldg(&bw[tid]);
    __syncthreads();
}

__global__ void __launch_bounds__(NT, 1) tts_decode_kernel(
    const float* __restrict__ past_k, const float* __restrict__ past_v,
    const float* __restrict__ hidden, const float* __restrict__ logits_scale,
    const float* __restrict__ mask_scale,
    const float* __restrict__ ln1_g, const float* __restrict__ ln1_b,
    const float* __restrict__ Wq, const float* __restrict__ bq,
    const float* __restrict__ Wk, const float* __restrict__ bk,
    const float* __restrict__ Wv, const float* __restrict__ bv,
    const float* __restrict__ Wo, const float* __restrict__ bo,
    const float* __restrict__ ln2_g, const float* __restrict__ ln2_b,
    const float* __restrict__ Wfc, const float* __restrict__ bfc,
    const float* __restrict__ Wmp, const float* __restrict__ bmp,
    const float* __restrict__ lnf_g, const float* __restrict__ lnf_b,
    const float* __restrict__ lm_w,
    float* __restrict__ out)
{
    __shared__ __align__(16) float sm[1024*4 + 8320 + 512 + 64];
    float* SX  = sm;                 // 1024: raw vec / q
    float* SP  = sm + 1024;          // 1024: v*g
    float* SG  = sm + 2048;          // 1024: g
    float* SB  = sm + 3072;          // 1024: b
    float* S4F = sm + 4096;          // 8320: reduce scratch
    float4* S4 = (float4*)S4F;
    float* SC  = sm + 12416;         // 512: probs / gelu / combine
    float* SR  = sm + 12928;         // 64: shuffle partials

    const int tid = threadIdx.x;
    const int bid = blockIdx.x;
    const int lane = tid & 31;
    const int w = tid >> 5;
    const float mskc = -128.0f * __ldg(&mask_scale[0]);

    // ---------------- init (flag-signaled) ----------------
    if (bid == 0) {
        g_hbuf[0][tid] = __ldg(&hidden[tid]);
        __threadfence(); __syncthreads();
        if (tid == 0) atomicAdd(&g_dInit, 1u);
    } else if (bid >= 1 && bid <= 3) {
        int mat = bid - 1;
        const float* bb = (mat == 0) ? bq : ((mat == 1) ? bk : bv);
        g_qkv[mat * DM + tid] = __ldg(&bb[tid]);
        __threadfence(); __syncthreads();
        if (tid == 0) atomicAdd(&g_fQB[0], 1u);
    } else if (bid == 129) {
        g_hbuf[1][tid] = __ldg(&bmp[0 * DM + tid]);   // seed layer-0 h_next
        __threadfence(); __syncthreads();
        if (tid == 0) atomicAdd(&g_fHN[0], 1u);
    }

    for (int l = 0; l < NL; l++) {
        const int p = l & 1;
        const float* h_in = g_hbuf[p];
        float* h_next = g_hbuf[p ^ 1];

        // ====== blocks 133-147: dedicated L2 prefetchers (one layer ahead) ======
        if (bid >= 133) {
            waitf((l == 0) ? &g_dInit : &g_dD[l - 1], (l == 0) ? 1u : 129u);
            int pb = bid - 133;                       // 0..14
            const int STRIDE = 15 * NT;               // 15360 threads total
            if (l + 1 < NL) {
                // next layer's Wq/Wk/Wv (3 x 32768 lines) + Wo (32768 lines)
                const float* Wqn = Wq + (size_t)(l + 1) * NHD * DM * HD;
                const float* Wkn = Wk + (size_t)(l + 1) * NHD * DM * HD;
                const float* Wvn = Wv + (size_t)(l + 1) * NHD * DM * HD;
                const float* Won = Wo + (size_t)(l + 1) * DM * DM;
                for (int idx = pb * NT + tid; idx < 32768; idx += STRIDE) {
                    pf_l2(Wqn + (size_t)idx * 32);
                    pf_l2(Wkn + (size_t)idx * 32);
                    pf_l2(Wvn + (size_t)idx * 32);
                    pf_l2(Won + (size_t)idx * 32);
                }
            }
            if (l >= NL - 2) {
                // lm_w: 262144 lines split over last two layers
                int half = l - (NL - 2);              // 0 or 1
                const float* base = lm_w + (size_t)half * 131072 * 32;
                for (int idx = pb * NT + tid; idx < 131072; idx += STRIDE)
                    pf_l2(base + (size_t)idx * 32);
            }
        }

        // ====== block 128: g_h2 = bo + h_in ======
        if (bid == 128) {
            waitf((l == 0) ? &g_dInit : &g_dD[l - 1], (l == 0) ? 1u : 129u);
            g_h2[tid] = __ldg(&bo[l * DM + tid]) + __ldcg(&h_in[tid]);
            __threadfence(); __syncthreads();
            if (tid == 0) atomicAdd(&g_fH2[l], 1u);
        }
        // ====== block 129: seed h_next = bmp (l>=1) ======
        if (bid == 129 && l >= 1) {
            waitf(&g_dA[l - 1], 96u);
            waitf(&g_fH2[l - 1], 1u);
            h_next[tid] = __ldg(&bmp[l * DM + tid]);
            __threadfence(); __syncthreads();
            if (tid == 0) atomicAdd(&g_fHN[l], 1u);
        }

        // ====== Stage A: QKV (96 blocks), LN linearized ======
        if (bid < 96) {
            int mat = bid % 3, rest = bid / 3, h = rest % NHD, half = rest / NHD;
            const float4* W4 = (const float4*)(
                ((mat == 0) ? Wq : ((mat == 1) ? Wk : Wv))
                + (size_t)l * NHD * DM * HD + (size_t)h * DM * HD);
            int d0 = half * 512;
            int e4 = tid & 15, dg = tid >> 4;
            float4 wa[4];
            #pragma unroll
            for (int it = 0; it < 4; it++)
                wa[it] = __ldcs(&W4[(size_t)(d0 + dg + it * 64) * 16 + e4]);
            #pragma unroll
            for (int it = 4; it < 8; it++)
                pf_l2(&W4[(size_t)(d0 + dg + it * 64) * 16 + e4]);
            float gg = __ldg(&ln1_g[l * DM + tid]);
            float bb = __ldg(&ln1_b[l * DM + tid]);
            waitf((l == 0) ? &g_dInit : &g_dD[l - 1], (l == 0) ? 1u : 129u);
            float v = __ldcg(&h_in[tid]);
            SP[tid] = v * gg; SG[tid] = gg; SB[tid] = bb;
            __syncthreads();
            float mean, rstd;
            ln_stats(v, SR, tid, mean, rstd);
            float4 aA = make_float4(0,0,0,0), aB = aA, aC = aA;
            #pragma unroll
            for (int it = 0; it < 4; it++) {
                int d = d0 + dg + it * 64;
                f4fma(aA, SP[d], wa[it]); f4fma(aB, SG[d], wa[it]); f4fma(aC, SB[d], wa[it]);
            }
            #pragma unroll
            for (int it = 4; it < 8; it++) {
                int d = d0 + dg + it * 64;
                float4 ww = __ldcs(&W4[(size_t)d * 16 + e4]);
                f4fma(aA, SP[d], ww); f4fma(aB, SG[d], ww); f4fma(aC, SB[d], ww);
            }
            float4 aD;       // fold LN before the tree
            aD.x = rstd * (aA.x - mean * aB.x) + aC.x;
            aD.y = rstd * (aA.y - mean * aB.y) + aC.y;
            aD.z = rstd * (aA.z - mean * aB.z) + aC.z;
            aD.w = rstd * (aA.w - mean * aB.w) + aC.w;
            aD = f4shfl_add(aD, 16);
            if (lane < 16) S4[w * 17 + lane] = aD;
            waitf(&g_fQB[l], 3u);                     // syncs; S4 visible
            if (w < 16) {
                float4 t = f4warp_sum(S4[lane * 17 + w]);
                if (lane == 0) {
                    float* dst = &g_qkv[mat * DM + h * HD + w * 4];
                    atomicAdd(dst,     t.x); atomicAdd(dst + 1, t.y);
                    atomicAdd(dst + 2, t.z); atomicAdd(dst + 3, t.w);
                }
            }
            __threadfence(); __syncthreads();
            if (tid == 0) {
                atomicAdd(&g_dA[l], 1u);
                if (mat == 0) atomicAdd(&g_dAqh[l][h], 1u);
                else          atomicAdd(&g_dAkvh[l][h], 1u);
            }
        }

        // ====== Stage B: attention (128 blocks) ======
        if (bid < 128) {
            int h = bid >> 3, c = bid & 7;
            int t0 = c * 256;
            int t = tid & 255, eg = tid >> 8;
            int tg = t0 + t;
            size_t kbase  = ((size_t)(l * NHD + h) * HD) * TPAST;
            size_t okbase = ((size_t)(l * NHD + h) * HD) * TKV;
            const bool isNew = (tg >= TPAST);
            float kreg[16];
            if (!isNew) {
                #pragma unroll
                for (int j = 0; j < 16; j++)
                    kreg[j] = __ldcs(&past_k[kbase + (size_t)(eg * 16 + j) * TPAST + tg]);
                #pragma unroll
                for (int j = 0; j < 16; j++)
                    __stcs(&out[okbase + (size_t)(eg * 16 + j) * TKV + tg], kreg[j]);
            }
            // prefetch V tile to L2 (overlaps stage A)
            int e4 = tid & 15, tgr = tid >> 4;
            const float4* pv4 = (const float4*)(past_v + ((size_t)(l * NHD + h) * TPAST) * HD);
            #pragma unroll
            for (int i = 0; i < 4; i++) {
                int tgl = t0 + tgr + 64 * i;
                if (tgl < TPAST) pf_l2(&pv4[(size_t)tgl * 16 + e4]);
            }
            waitf(&g_dAqh[l][h], 2u);                 // q ready (2 producers)
            if (c == 7) waitf(&g_dAkvh[l][h], 4u);    // k_new/v_new ready
            if (isNew) {
                #pragma unroll
                for (int j = 0; j < 16; j++) {
                    kreg[j] = __ldcg(&g_qkv[DM + h * HD + eg * 16 + j]);
                    __stcs(&out[okbase + (size_t)(eg * 16 + j) * TKV + tg], kreg[j]);
                }
            }
            if (tid < 64) SX[tid] = __ldcg(&g_qkv[h * HD + tid]);  // q
            __syncthreads();
            float part = 0.0f;
            #pragma unroll
            for (int j = 0; j < 16; j++) part += SX[eg * 16 + j] * kreg[j];
            S4F[eg * 256 + t] = part;
            __syncthreads();

            // V actual loads (L2-warm) + fused copy
            float4* ov4 = (float4*)(out + (size_t)KS_ELEMS + ((size_t)(l * NHD + h) * TKV) * HD);
            const float4* vnew4 = (const float4*)(g_qkv + 2 * DM + h * HD);
            float4 vreg[4];
            #pragma unroll
            for (int i = 0; i < 4; i++) {
                int tgl = t0 + tgr + 64 * i;
                vreg[i] = (tgl < TPAST) ? __ldcs(&pv4[(size_t)tgl * 16 + e4])
                                        : __ldcg(&vnew4[e4]);
            }
            #pragma unroll
            for (int i = 0; i < 4; i++)
                __stcs(&ov4[(size_t)(t0 + tgr + 64 * i) * 16 + e4], vreg[i]);

            float sc = -1e30f;
            if (tid < 256) {
                sc = S4F[t] + S4F[256 + t] + S4F[512 + t] + S4F[768 + t];
                if (tg > 0) sc += mskc;
            }
            float mx = sc;
            #pragma unroll
            for (int o = 16; o; o >>= 1) mx = fmaxf(mx, __shfl_xor_sync(0xffffffffu, mx, o));
            if (lane == 0) SR[w] = mx;
            __syncthreads();
            if (w == 0) {
                float m2 = (lane < 8) ? SR[lane] : -1e30f;
                #pragma unroll
                for (int o = 16; o; o >>= 1) m2 = fmaxf(m2, __shfl_xor_sync(0xffffffffu, m2, o));
                if (lane == 0) SR[40] = m2;
            }
            __syncthreads();
            float M = SR[40];
            float pe = 0.0f;
            if (tid < 256) { pe = __expf(sc - M); SC[t] = pe; }
            float sum = pe;
            #pragma unroll
            for (int o = 16; o; o >>= 1) sum += __shfl_xor_sync(0xffffffffu, sum, o);
            if (lane == 0) SR[w] = sum;
            __syncthreads();
            if (w == 0) {
                float s2 = (lane < 8) ? SR[lane] : 0.0f;
                #pragma unroll
                for (int o = 16; o; o >>= 1) s2 += __shfl_xor_sync(0xffffffffu, s2, o);
                if (lane == 0) SR[41] = s2;
            }
            __syncthreads();

            float4 acc = make_float4(0,0,0,0);
            #pragma unroll
            for (int i = 0; i < 4; i++) f4fma(acc, SC[tgr + 64 * i], vreg[i]);
            acc = f4shfl_add(acc, 16);
            if (lane < 16) S4[w * 17 + lane] = acc;
            __syncthreads();
            if (tid == 0) { __stcg(&g_m[h][c], M); __stcg(&g_se[h][c], SR[41]); }
            if (w < 16) {
                float4 t2 = f4warp_sum(S4[lane * 17 + w]);
                if (lane == 0) __stcg((float4*)&g_acc[h][c][w * 4], t2);
            }
            __threadfence(); __syncthreads();
            if (tid == 0) { atomicAdd(&g_dBh[l][h], 1u); atomicAdd(&g_dB[l], 1u); }
        }

        // ====== blocks 130-132: seed next layer's qkv bias ======
        if (bid >= 130 && bid <= 132 && (l + 1) < NL) {
            waitf(&g_dB[l], 128u);
            int mat = bid - 130;
            const float* bb = (mat == 0) ? bq : ((mat == 1) ? bk : bv);
            g_qkv[mat * DM + tid] = __ldg(&bb[(l + 1) * DM + tid]);
            __threadfence(); __syncthreads();
            if (tid == 0) atomicAdd(&g_fQB[l + 1], 1u);
        }

        // ====== Stage C: combine + c_proj (128 blocks x 8 rows) ======
        if (bid < 128) {
            int r0 = bid * 8, h = r0 >> 6, e0 = r0 & 63;
            // prefetch DE tiles to L2 (overlaps stage B/C)
            {
                int qx = tid & 7, dgx = tid >> 3;
                const float4* Wf4p = (const float4*)(Wfc + (size_t)l * DM * FF);
                #pragma unroll
                for (int it = 0; it < 8; it++)
                    pf_l2(&Wf4p[(size_t)(dgx + it * 128) * 1024 + bid * 8 + qx]);
                int c4x = tid & 255, jgx = tid >> 8;
                const float4* Wm4p = (const float4*)(Wmp + (size_t)l * FF * DM + (size_t)(bid * 32) * DM);
                #pragma unroll
                for (int jj = 0; jj < 8; jj++)
                    pf_l2(&Wm4p[(size_t)(jgx + 4 * jj) * 256 + c4x]);
            }
            int c4 = tid & 255, jg = tid >> 8;
            const float4* Wo4 = (const float4*)(Wo + (size_t)l * DM * DM + (size_t)r0 * DM);
            float4 wo0 = __ldcs(&Wo4[(size_t)jg * 256 + c4]);
            float4 wo1 = __ldcs(&Wo4[(size_t)(jg + 4) * 256 + c4]);
            waitf(&g_dBh[l][h], 8u);                  // this head's chunks only
            if (tid < 32) {
                float m = (lane < 8) ? __ldcg(&g_m[h][lane]) : -1e30f;
                float M = m;
                #pragma unroll
                for (int o = 16; o; o >>= 1) M = fmaxf(M, __shfl_xor_sync(0xffffffffu, M, o));
                float wc  = (lane < 8) ? __expf(m - M) : 0.0f;
                float den = (lane < 8) ? wc * __ldcg(&g_se[h][lane]) : 0.0f;
                #pragma unroll
                for (int o = 16; o; o >>= 1) den += __shfl_xor_sync(0xffffffffu, den, o);
                if (lane < 8) SC[lane] = wc;
                if (lane == 0) SC[8] = den;
            }
            __syncthreads();
            if (tid < 64) {
                int cc = tid >> 3, e8 = tid & 7;
                SC[16 + cc * 8 + e8] = SC[cc] * __ldcg(&g_acc[h][cc][e0 + e8]);
            }
            __syncthreads();
            if (tid < 8) {
                float s = 0.0f;
                #pragma unroll
                for (int cc = 0; cc < 8; cc++) s += SC[16 + cc * 8 + tid];
                SC[80 + tid] = s / SC[8];
            }
            __syncthreads();
            float4 acc = make_float4(0,0,0,0);
            f4fma(acc, SC[80 + jg], wo0);
            f4fma(acc, SC[80 + jg + 4], wo1);
            S4[jg * 256 + c4] = acc;
            #pragma unroll
            for (int s = 2; s; s >>= 1) {
                __syncthreads();
                if (jg < s) f4add(S4[jg * 256 + c4], S4[(jg + s) * 256 + c4]);
            }
            __syncthreads();
            waitf(&g_fH2[l], 1u);
            atomicAdd(&g_h2[tid], S4F[tid]);
            __threadfence(); __syncthreads();
            if (tid == 0) atomicAdd(&g_dC[l], 1u);
        }

        // ====== Stage DE: fused MLP (128 blocks), LN linearized ======
        if (bid < 128) {
            int q = tid & 7, dg = tid >> 3;
            const float4* Wf4 = (const float4*)(Wfc + (size_t)l * DM * FF);
            float4 wf[4];
            #pragma unroll
            for (int it = 0; it < 4; it++)
                wf[it] = __ldcs(&Wf4[(size_t)(dg + it * 128) * 1024 + bid * 8 + q]);
            float gg = __ldg(&ln2_g[l * DM + tid]);
            float bb = __ldg(&ln2_b[l * DM + tid]);
            waitf(&g_dC[l], 128u);
            float v = __ldcg(&g_h2[tid]);
            SP[tid] = v * gg; SG[tid] = gg; SB[tid] = bb;
            __syncthreads();
            float mean, rstd;
            ln_stats(v, SR, tid, mean, rstd);
            float4 aA = make_float4(0,0,0,0), aB = aA, aC = aA;
            #pragma unroll
            for (int it = 0; it < 4; it++) {
                int d = dg + it * 128;
                f4fma(aA, SP[d], wf[it]); f4fma(aB, SG[d], wf[it]); f4fma(aC, SB[d], wf[it]);
            }
            #pragma unroll
            for (int it = 4; it < 8; it++) {
                int d = dg + it * 128;
                float4 ww = __ldcs(&Wf4[(size_t)d * 1024 + bid * 8 + q]);
                f4fma(aA, SP[d], ww); f4fma(aB, SG[d], ww); f4fma(aC, SB[d], ww);
            }
            float4 aD;
            aD.x = rstd * (aA.x - mean * aB.x) + aC.x;
            aD.y = rstd * (aA.y - mean * aB.y) + aC.y;
            aD.z = rstd * (aA.z - mean * aB.z) + aC.z;
            aD.w = rstd * (aA.w - mean * aB.w) + aC.w;
            aD = f4shfl_add(aD, 8);
            aD = f4shfl_add(aD, 16);
            if (lane < 8) S4[w * 9 + lane] = aD;
            // Wmp loads (L2-warm from stage-C prefetch) overlap FC tree
            int c4 = tid & 255, jg = tid >> 8;
            const float4* Wm4 = (const float4*)(Wmp + (size_t)l * FF * DM + (size_t)(bid * 32) * DM);
            float4 wm[8];
            #pragma unroll
            for (int jj = 0; jj < 8; jj++)
                wm[jj] = __ldcs(&Wm4[(size_t)(jg + 4 * jj) * 256 + c4]);
            __syncthreads();
            if (w < 8) {
                float4 t = f4warp_sum(S4[lane * 9 + w]);
                if (lane == 0) {
                    const float* bfp = &bfc[l * FF + bid * 32 + w * 4];
                    SC[w * 4 + 0] = gelu_tanh(t.x + __ldg(&bfp[0]));
                    SC[w * 4 + 1] = gelu_tanh(t.y + __ldg(&bfp[1]));
                    SC[w * 4 + 2] = gelu_tanh(t.z + __ldg(&bfp[2]));
                    SC[w * 4 + 3] = gelu_tanh(t.w + __ldg(&bfp[3]));
                }
            }
            __syncthreads();
            float4 acc2 = make_float4(0,0,0,0);
            #pragma unroll
            for (int jj = 0; jj < 8; jj++)
                f4fma(acc2, SC[jg + 4 * jj], wm[jj]);
            S4[jg * 256 + c4] = acc2;
            #pragma unroll
            for (int s = 2; s; s >>= 1) {
                __syncthreads();
                if (jg < s) f4add(S4[jg * 256 + c4], S4[(jg + s) * 256 + c4]);
            }
            __syncthreads();
            waitf(&g_fHN[l], 1u);
            atomicAdd(&h_next[tid], S4F[tid]);
            __threadfence(); __syncthreads();
            if (tid == 0) atomicAdd(&g_dD[l], 1u);
        }
        // block 128: residual h2 -> h_next
        if (bid == 128) {
            waitf(&g_dC[l], 128u);
            waitf(&g_fHN[l], 1u);
            atomicAdd(&h_next[tid], __ldcg(&g_h2[tid]));
            __threadfence(); __syncthreads();
            if (tid == 0) atomicAdd(&g_dD[l], 1u);    // total target 129
        }
    }

    // ====== Final: LN + logits (float2, shallow tree) + argmax ======
    waitf(&g_dD[NL - 1], 129u);
    ln_vec(g_hbuf[0], lnf_g, lnf_b, SX, SR, tid);
    if (bid == 0) {
        if (tid == 0) out[2 * (size_t)KS_ELEMS] = (float)TKV;
        out[2 * (size_t)KS_ELEMS + 1 + tid] = SX[tid];
    }
    {
        int cb = bid * 64;
        if (cb < VOC) {
            int c2 = lane, dg = w;
            int col = cb + c2 * 2;
            float2 acc = make_float2(0.f, 0.f);
            if (col < VOC) {
                const float2* L2p = (const float2*)lm_w;
                for (int d = dg; d < DM; d += 32) {
                    float xv = SX[d];
                    float2 wv = __ldcs(&L2p[(size_t)d * (VOC / 2) + (cb >> 1) + c2]);
                    acc.x += xv * wv.x; acc.y += xv * wv.y;
                }
            }
            S4F[dg * 65 + c2 * 2]     = acc.x;
            S4F[dg * 65 + c2 * 2 + 1] = acc.y;
            __syncthreads();
            float s0 = S4F[lane * 65 + 2 * w];
            float s1 = S4F[lane * 65 + 2 * w + 1];
            #pragma unroll
            for (int o = 16; o; o >>= 1) {
                s0 += __shfl_xor_sync(0xffffffffu, s0, o);
                s1 += __shfl_xor_sync(0xffffffffu, s1, o);
            }
            if (lane == 0) {
                #pragma unroll
                for (int k = 0; k < 2; k++) {
                    int col2 = cb + 2 * w + k;
                    if (col2 < VOC) {
                        float logit = (k ? s1 : s0) * __ldg(&logits_scale[col2]);
                        unsigned u = __float_as_uint(logit);
                        u = (u & 0x80000000u) ? ~u : (u | 0x80000000u);
                        unsigned long long key =
                            ((unsigned long long)u << 32) |
                            (unsigned long long)(0xFFFFFFFFu - (unsigned)col2);
                        atomicMax(&g_best, key);
                    }
                }
            }
        }
    }
    gbar();

    if (bid == 0) {
        if (tid == 0) {
            unsigned long long b = atomicMax(&g_best, 0ull);
            unsigned col = 0xFFFFFFFFu - (unsigned)(b & 0xFFFFFFFFull);
            out[2 * (size_t)KS_ELEMS + 1 + DM] = (float)col;
            g_best = 0ull;
            g_dInit = 0u;
        }
        if (tid < NL) {
            g_dA[tid] = 0u; g_dB[tid] = 0u; g_dC[tid] = 0u; g_dD[tid] = 0u;
            g_fQB[tid] = 0u; g_fH2[tid] = 0u; g_fHN[tid] = 0u;
        }
        if (tid < NL * NHD) {
            ((unsigned*)g_dAqh)[tid] = 0u;
            ((unsigned*)g_dAkvh)[tid] = 0u;
            ((unsigned*)g_dBh)[tid] = 0u;
        }
    }
}

extern "C" void kernel_launch(void* const* d_in, const int* in_sizes, int n_in,
                              void* d_out, int out_size) {
    const float* past_k       = (const float*)d_in[0];
    const float* past_v       = (const float*)d_in[1];
    const float* hidden       = (const float*)d_in[2];
    const float* logits_scale = (const float*)d_in[3];
    const float* mask_scale   = (const float*)d_in[4];
    const float* ln1_g        = (const float*)d_in[5];
    const float* ln1_b        = (const float*)d_in[6];
    const float* Wq           = (const float*)d_in[7];
    const float* bq           = (const float*)d_in[8];
    const float* Wk           = (const float*)d_in[9];
    const float* bk           = (const float*)d_in[10];
    const float* Wv           = (const float*)d_in[11];
    const float* bv           = (const float*)d_in[12];
    const float* Wo           = (const float*)d_in[13];
    const float* bo           = (const float*)d_in[14];
    const float* ln2_g        = (const float*)d_in[15];
    const float* ln2_b        = (const float*)d_in[16];
    const float* Wfc          = (const float*)d_in[17];
    const float* bfc          = (const float*)d_in[18];
    const float* Wmp          = (const float*)d_in[19];
    const float* bmp          = (const float*)d_in[20];
    const float* lnf_g        = (const float*)d_in[21];
    const float* lnf_b        = (const float*)d_in[22];
    const float* lm_w         = (const float*)d_in[23];
    float* outp = (float*)d_out;

    tts_decode_kernel<<<NB, NT>>>(past_k, past_v, hidden, logits_scale, mask_scale,
                                  ln1_g, ln1_b, Wq, bq, Wk, bk, Wv, bv, Wo, bo,
                                  ln2_g, ln2_b, Wfc, bfc, Wmp, bmp,
                                  lnf_g, lnf_b, lm_w, outp);
}